// round 7
// baseline (speedup 1.0000x reference)
#include <cuda_runtime.h>
#include <cuda_bf16.h>

#define NG 1024
#define NP 512   // gaussian pairs
#define HH 768
#define WW 768
#define TPX 16   // pixels per thread along w (8 f32x2 pairs)

typedef unsigned long long u64;

// Pair-packed SoA, 12 u64 (24 floats) per gaussian pair:
// slot0 {-mx0,-mx1} slot1 {-my0,-my1} slot2 {A0,A1} slot3 {B0,B1}
// slot4 {D0,D1} slot5 {Dm0,Dm1} slot6 {Dm20,Dm21}
// slot7 {s0,s3_0} slot8 {s1,s3_1} slot9 {wr0,wg0} slot10 {wr1,wg1} slot11 {wb0,wb1}
__device__ __align__(16) float g_coef2[NP * 24];

__device__ __forceinline__ u64 pk2(float lo, float hi) {
    u64 d; asm("mov.b64 %0, {%1, %2};" : "=l"(d) : "f"(lo), "f"(hi)); return d;
}
__device__ __forceinline__ void upk2(u64 v, float& lo, float& hi) {
    asm("mov.b64 {%0, %1}, %2;" : "=f"(lo), "=f"(hi) : "l"(v));
}
__device__ __forceinline__ u64 fma2(u64 a, u64 b, u64 c) {
    u64 d; asm("fma.rn.f32x2 %0, %1, %2, %3;" : "=l"(d) : "l"(a), "l"(b), "l"(c)); return d;
}
__device__ __forceinline__ u64 mul2(u64 a, u64 b) {
    u64 d; asm("mul.rn.f32x2 %0, %1, %2;" : "=l"(d) : "l"(a), "l"(b)); return d;
}
__device__ __forceinline__ u64 add2(u64 a, u64 b) {
    u64 d; asm("add.rn.f32x2 %0, %1, %2;" : "=l"(d) : "l"(a), "l"(b)); return d;
}
__device__ __forceinline__ float ex2f(float a) {
    float v; asm("ex2.approx.ftz.f32 %0, %1;" : "=f"(v) : "f"(a)); return v;
}

__global__ void prep_kernel(const float* __restrict__ means,
                            const float* __restrict__ cov,
                            const float* __restrict__ colors) {
    int n = blockIdx.x * blockDim.x + threadIdx.x;
    if (n >= NG) return;
    float mx = means[2 * n + 0];
    float my = means[2 * n + 1];
    float a = cov[4 * n + 0];
    float b = cov[4 * n + 1];
    float c = cov[4 * n + 2];
    float d = cov[4 * n + 3];
    float det = a * d - b * c;
    float ia  = d / det;
    float ibc = (-b - c) / det;
    float idd = a / det;
    const float k = -0.72134752044448170368f;  // -0.5 * log2(e)
    float A = k * ia;
    float B = k * ibc;
    float D = k * idd;
    float Dm  = -2.0f * D * my;
    float Dm2 = D * my * my;
    const float delta = 1.0f / 767.0f;
    float s  = exp2f(2.0f * D * delta * delta);
    float s3 = s * s * s;
    float cr = colors[4 * n + 0];
    float cg = colors[4 * n + 1];
    float cb = colors[4 * n + 2];
    float al = colors[4 * n + 3];
    float wr = al / (1.0f + __expf(-cr));
    float wg = al / (1.0f + __expf(-cg));
    float wb = al / (1.0f + __expf(-cb));

    int l = n & 1;
    float* o = g_coef2 + (n >> 1) * 24;
    o[0 + l]  = -mx;
    o[2 + l]  = -my;
    o[4 + l]  = A;
    o[6 + l]  = B;
    o[8 + l]  = D;
    o[10 + l] = Dm;
    o[12 + l] = Dm2;
    o[14 + 2 * l] = s;
    o[15 + 2 * l] = s3;
    o[18 + 2 * l] = wr;
    o[19 + 2 * l] = wg;
    o[22 + l] = wb;
}

// Block: 128 threads = 8 segments (16 px each) x 16 rows; tile 128x16. Grid (6, 48).
__global__ __launch_bounds__(128)
void render_kernel(float* __restrict__ out) {
    __shared__ u64 sh[NP * 12];  // 48 KB
    {
        const float4* gc = (const float4*)g_coef2;
        float4* sf = (float4*)sh;
        #pragma unroll 8
        for (int i = threadIdx.x; i < NP * 6; i += 128) sf[i] = gc[i];
    }
    __syncthreads();

    int tid = threadIdx.x;
    int seg = tid & 7;
    int row = tid >> 3;
    int h  = blockIdx.y * 16 + row;
    int w0 = blockIdx.x * 128 + seg * TPX;

    const float inv = 1.0f / 767.0f;
    float x  = (float)h * inv;
    float y0 = (float)w0 * inv;

    u64 x2      = pk2(x, x);
    u64 y0_2    = pk2(y0, y0);
    u64 y0sq_2  = pk2(y0 * y0, y0 * y0);
    float c2y0d = 2.0f * y0 + inv;
    u64 c2y0d_2 = pk2(c2y0d, c2y0d);
    u64 inv2    = pk2(inv, inv);

    u64 ar2[TPX / 2], ag2[TPX / 2], ab2[TPX / 2];
    #pragma unroll
    for (int kk = 0; kk < TPX / 2; kk++) { ar2[kk] = 0ull; ag2[kk] = 0ull; ab2[kk] = 0ull; }

    #pragma unroll 1
    for (int p = 0; p < NP; p++) {
        const u64* cp = sh + p * 12;
        u64 nmx2  = cp[0];
        u64 nmy2  = cp[1];
        u64 A2    = cp[2];
        u64 B2    = cp[3];
        u64 D2    = cp[4];
        u64 Dm_2  = cp[5];
        u64 Dm2_2 = cp[6];

        // Packed-over-gaussians hoist: arg(y) = e0 + e1*y + D*y^2
        u64 dx2 = add2(x2, nmx2);
        u64 t2  = mul2(A2, dx2);
        u64 c12 = mul2(B2, dx2);
        u64 c02 = fma2(t2, dx2, Dm2_2);
        u64 e12 = add2(c12, Dm_2);
        u64 e02 = fma2(nmy2, c12, c02);

        u64 arg2 = fma2(e12, y0_2, fma2(D2, y0sq_2, e02));
        u64 rrg2 = mul2(inv2, fma2(D2, c2y0d_2, e12));

        float a0, a1, rr0, rr1;
        upk2(arg2, a0, a1);
        upk2(rrg2, rr0, rr1);
        float v0a = ex2f(a0);
        float r0a = ex2f(rr0);
        float v0b = ex2f(a1);
        float r0b = ex2f(rr1);

        float wb0, wb1;
        upk2(cp[11], wb0, wb1);

        #pragma unroll
        for (int g = 0; g < 2; g++) {
            float v0 = g ? v0b : v0a;
            float r0 = g ? r0b : r0a;
            u64 sp   = cp[7 + g];       // {s, s^3}
            u64 wrg  = cp[9 + g];       // {wr, wg}
            float wb = g ? wb1 : wb0;

            float s, s3;
            upk2(sp, s, s3);
            float s4 = s * s3;
            u64 S4 = pk2(s4, s4);
            float v1  = v0 * r0;
            float r0q = r0 * r0;
            u64 P = mul2(pk2(r0q, r0q), sp);   // {r0^2*s, r0^2*s^3}
            u64 V = pk2(v0, v1);

            float wr, wg;
            upk2(wrg, wr, wg);
            u64 wr2 = pk2(wr, wr);
            u64 wg2 = pk2(wg, wg);
            u64 wb2 = pk2(wb, wb);

            #pragma unroll
            for (int kk = 0; kk < TPX / 2; kk++) {
                ar2[kk] = fma2(V, wr2, ar2[kk]);
                ag2[kk] = fma2(V, wg2, ag2[kk]);
                ab2[kk] = fma2(V, wb2, ab2[kk]);
                if (kk < TPX / 2 - 1) {
                    V = mul2(V, P);
                    if (kk < TPX / 2 - 2) P = mul2(P, S4);
                }
            }
        }
    }

    // Unpack and store: 48 contiguous floats per thread -> 12 x STG.128
    float r[TPX], g[TPX], b[TPX];
    #pragma unroll
    for (int kk = 0; kk < TPX / 2; kk++) {
        upk2(ar2[kk], r[2 * kk], r[2 * kk + 1]);
        upk2(ag2[kk], g[2 * kk], g[2 * kk + 1]);
        upk2(ab2[kk], b[2 * kk], b[2 * kk + 1]);
    }
    float buf[TPX * 3];
    #pragma unroll
    for (int j = 0; j < TPX; j++) {
        buf[3 * j + 0] = r[j];
        buf[3 * j + 1] = g[j];
        buf[3 * j + 2] = b[j];
    }
    float4* o = (float4*)(out + ((size_t)h * WW + w0) * 3);
    #pragma unroll
    for (int q = 0; q < TPX * 3 / 4; q++) o[q] = ((float4*)buf)[q];
}

extern "C" void kernel_launch(void* const* d_in, const int* in_sizes, int n_in,
                              void* d_out, int out_size) {
    const float* means  = (const float*)d_in[0];
    const float* cov    = (const float*)d_in[1];
    const float* colors = (const float*)d_in[2];
    float* out = (float*)d_out;

    prep_kernel<<<4, 256>>>(means, cov, colors);
    dim3 grid(WW / 128, HH / 16);
    render_kernel<<<grid, 128>>>(out);
}

// round 8
// speedup vs baseline: 1.0504x; 1.0504x over previous
#include <cuda_runtime.h>
#include <cuda_bf16.h>

#define NG 1024
#define HH 768
#define WW 768
#define TPX 16   // pixels per thread along w (8 f32x2 pairs)

// Per-gaussian coefficients, 12 floats (3 x float4):
// [0]=mx [1]=-my [2]=A [3]=B | [4]=D [5]=Dm [6]=Dm2 [7]=s | [8]=wr [9]=wg [10]=wb [11]=s3
// A,B,D already scaled by -0.5*log2(e); s = 2^(2*D*delta^2), s3 = s^3
__device__ __align__(16) float g_coef[NG * 12];

typedef unsigned long long u64;

__device__ __forceinline__ u64 pk2(float lo, float hi) {
    u64 d; asm("mov.b64 %0, {%1, %2};" : "=l"(d) : "f"(lo), "f"(hi)); return d;
}
__device__ __forceinline__ void upk2(u64 v, float& lo, float& hi) {
    asm("mov.b64 {%0, %1}, %2;" : "=f"(lo), "=f"(hi) : "l"(v));
}
__device__ __forceinline__ u64 fma2(u64 a, u64 b, u64 c) {
    u64 d; asm("fma.rn.f32x2 %0, %1, %2, %3;" : "=l"(d) : "l"(a), "l"(b), "l"(c)); return d;
}
__device__ __forceinline__ u64 mul2(u64 a, u64 b) {
    u64 d; asm("mul.rn.f32x2 %0, %1, %2;" : "=l"(d) : "l"(a), "l"(b)); return d;
}
__device__ __forceinline__ float ex2f(float a) {
    float v; asm("ex2.approx.ftz.f32 %0, %1;" : "=f"(v) : "f"(a)); return v;
}

__global__ void prep_kernel(const float* __restrict__ means,
                            const float* __restrict__ cov,
                            const float* __restrict__ colors) {
    int n = blockIdx.x * blockDim.x + threadIdx.x;
    if (n >= NG) return;
    float mx = means[2 * n + 0];
    float my = means[2 * n + 1];
    float a = cov[4 * n + 0];
    float b = cov[4 * n + 1];
    float c = cov[4 * n + 2];
    float d = cov[4 * n + 3];
    float det = a * d - b * c;
    float ia  = d / det;
    float ibc = (-b - c) / det;   // ib + ic
    float idd = a / det;
    const float k = -0.72134752044448170368f;  // -0.5 * log2(e)
    float A = k * ia;
    float B = k * ibc;
    float D = k * idd;
    float Dm  = -2.0f * D * my;
    float Dm2 = D * my * my;
    const float delta = 1.0f / 767.0f;
    float s  = exp2f(2.0f * D * delta * delta);
    float s3 = s * s * s;
    float cr = colors[4 * n + 0];
    float cg = colors[4 * n + 1];
    float cb = colors[4 * n + 2];
    float al = colors[4 * n + 3];
    float wr = al / (1.0f + __expf(-cr));
    float wg = al / (1.0f + __expf(-cg));
    float wb = al / (1.0f + __expf(-cb));
    float* o = g_coef + 12 * n;
    o[0] = mx; o[1] = -my; o[2] = A;   o[3] = B;
    o[4] = D;  o[5] = Dm;  o[6] = Dm2; o[7] = s;
    o[8] = wr; o[9] = wg;  o[10] = wb; o[11] = s3;
}

// Block: 128 threads = 8 segments (16 px each, 128 px wide) x 16 rows.
// Grid (768/128, 768/16) = (6, 48) = 288 blocks.
__global__ __launch_bounds__(128)
void render_kernel(float* __restrict__ out) {
    __shared__ float4 sh[NG * 3];  // 48 KB
    {
        const float4* gc = (const float4*)g_coef;
        #pragma unroll 8
        for (int i = threadIdx.x; i < NG * 3; i += 128) sh[i] = gc[i];
    }
    __syncthreads();

    int tid = threadIdx.x;
    int seg = tid & 7;     // 0..7 -> which 16-pixel segment
    int row = tid >> 3;    // 0..15 -> row within tile
    int h  = blockIdx.y * 16 + row;
    int w0 = blockIdx.x * 128 + seg * TPX;

    const float inv = 1.0f / 767.0f;   // delta
    float x  = (float)h * inv;
    float y0 = (float)w0 * inv;
    float y0sq   = y0 * y0;
    float c2y0d  = 2.0f * y0 + inv;    // (2*y0 + delta), for r0 arg

    u64 ar2[TPX / 2], ag2[TPX / 2], ab2[TPX / 2];
    #pragma unroll
    for (int kk = 0; kk < TPX / 2; kk++) { ar2[kk] = 0ull; ag2[kk] = 0ull; ab2[kk] = 0ull; }

    #pragma unroll 4
    for (int n = 0; n < NG; n++) {
        float4 p0 = sh[3 * n + 0];
        float4 p1 = sh[3 * n + 1];
        float4 p2 = sh[3 * n + 2];
        float mx  = p0.x, nmy = p0.y, A = p0.z, B = p0.w;
        float D   = p1.x, Dm  = p1.y, Dm2 = p1.z, s = p1.w;
        u64 wr2 = pk2(p2.x, p2.x);
        u64 wg2 = pk2(p2.y, p2.y);
        u64 wb2 = pk2(p2.z, p2.z);
        float s3 = p2.w;

        // Hoist per (gaussian, row): arg(y) = e0 + e1*y + D*y^2
        float dx = x - mx;
        float t  = A * dx;
        float c1 = B * dx;
        float c0 = fmaf(t, dx, Dm2);
        float e1 = c1 + Dm;
        float e0 = fmaf(nmy, c1, c0);

        // v0 = 2^(arg at y0); r0 = v1/v0 = 2^(delta*(e1 + D*(2*y0+delta)))
        float arg0  = fmaf(e1, y0, fmaf(D, y0sq, e0));
        float rarg  = inv * fmaf(D, c2y0d, e1);
        float v0 = ex2f(arg0);
        float r0 = ex2f(rarg);

        float s4 = s * s3;
        float v1  = v0 * r0;
        float r0q = r0 * r0;
        u64 V  = pk2(v0, v1);
        u64 P  = mul2(pk2(r0q, r0q), pk2(s, s3));   // {r0^2*s, r0^2*s^3}
        u64 S4 = pk2(s4, s4);

        #pragma unroll
        for (int kk = 0; kk < TPX / 2; kk++) {
            ar2[kk] = fma2(V, wr2, ar2[kk]);
            ag2[kk] = fma2(V, wg2, ag2[kk]);
            ab2[kk] = fma2(V, wb2, ab2[kk]);
            if (kk < TPX / 2 - 1) {
                V = mul2(V, P);
                if (kk < TPX / 2 - 2) P = mul2(P, S4);
            }
        }
    }

    // Unpack and store: 48 contiguous floats per thread -> 12 x STG.128
    float r[TPX], g[TPX], b[TPX];
    #pragma unroll
    for (int kk = 0; kk < TPX / 2; kk++) {
        upk2(ar2[kk], r[2 * kk], r[2 * kk + 1]);
        upk2(ag2[kk], g[2 * kk], g[2 * kk + 1]);
        upk2(ab2[kk], b[2 * kk], b[2 * kk + 1]);
    }
    float buf[TPX * 3];
    #pragma unroll
    for (int j = 0; j < TPX; j++) {
        buf[3 * j + 0] = r[j];
        buf[3 * j + 1] = g[j];
        buf[3 * j + 2] = b[j];
    }
    float4* o = (float4*)(out + ((size_t)h * WW + w0) * 3);
    #pragma unroll
    for (int q = 0; q < TPX * 3 / 4; q++) o[q] = ((float4*)buf)[q];
}

extern "C" void kernel_launch(void* const* d_in, const int* in_sizes, int n_in,
                              void* d_out, int out_size) {
    const float* means  = (const float*)d_in[0];
    const float* cov    = (const float*)d_in[1];
    const float* colors = (const float*)d_in[2];
    float* out = (float*)d_out;

    prep_kernel<<<4, 256>>>(means, cov, colors);
    dim3 grid(WW / 128, HH / 16);
    render_kernel<<<grid, 128>>>(out);
}